// round 10
// baseline (speedup 1.0000x reference)
#include <cuda_runtime.h>
#include <cuda_fp16.h>
#include <cstdint>

// Problem constants.
#define NB 8192
#define NH 1024
#define NO 256
#define NE 16

// GEMM tiling: CTA = 64(M) x 128(N), K slabs of 32 halfs, 4-stage pipeline.
#define BM 64
#define BN 128
#define BKS 32
#define NSLAB (NH / BKS)   // 32
#define THREADS 256
#define STAGES 4
#define A_STAGE_B 4096                  // 64 rows x 64 B (packed)
#define B_STAGE_B 8192                  // 128 rows x 64 B (packed)
#define A_OFF 0
#define B_OFF (STAGES * A_STAGE_B)      // 16384
#define BIAS_OFF (B_OFF + STAGES * B_STAGE_B)   // 49152
#define PRM_OFF (BIAS_OFF + BN * 4)             // 49664
#define MBAR_OFF (PRM_OFF + BM * 4)             // 49920
#define SMEM_TOTAL (MBAR_OFF + 64)              // 49984

// --- scratch (no allocs allowed) ---
__device__ int    g_perm[NB];
__device__ int    g_off[NE + 1];
__device__ int    g_counts[NE];
__device__ __half x16[NB * NH];                   // x in fp16, original row order
__device__ __half W16t[NE * 2 * NSLAB * 128 * 32]; // W fp16, tiled [e][nt][slab][row][32]

// ---------------- fused prep: bin (1 block) + x convert + W convert ----------------
// grid = 4097 x 256: blocks [0,2048) x rows, [2048,4096) W rows, block 4096 = bin.
__global__ __launch_bounds__(256)
void prep_kernel(const float* __restrict__ x, const float* __restrict__ W,
                 const int* __restrict__ num, const int* __restrict__ c, int cmap_n) {
    const int b = blockIdx.x;
    const int t = threadIdx.x;
    if (b < 2048) {
        // x convert: 4 rows per block, fp32 -> fp16, same layout
        const int row = b * 4 + (t >> 6);
        const int col = (t & 63) * 16;
        const float* src = x + (size_t)row * NH + col;
        float4 v0 = ((const float4*)src)[0];
        float4 v1 = ((const float4*)src)[1];
        float4 v2 = ((const float4*)src)[2];
        float4 v3 = ((const float4*)src)[3];
        __half2 h[8];
        h[0] = __floats2half2_rn(v0.x, v0.y);
        h[1] = __floats2half2_rn(v0.z, v0.w);
        h[2] = __floats2half2_rn(v1.x, v1.y);
        h[3] = __floats2half2_rn(v1.z, v1.w);
        h[4] = __floats2half2_rn(v2.x, v2.y);
        h[5] = __floats2half2_rn(v2.z, v2.w);
        h[6] = __floats2half2_rn(v3.x, v3.y);
        h[7] = __floats2half2_rn(v3.z, v3.w);
        __half* dst = x16 + (size_t)row * NH + col;
        ((uint4*)dst)[0] = *(uint4*)&h[0];
        ((uint4*)dst)[1] = *(uint4*)&h[4];
    } else if (b < 4096) {
        // W convert into tiled layout: 2 global W rows per block
        const int og = (b - 2048) * 2 + (t >> 7);   // global output row 0..4095
        const int e  = og >> 8;
        const int o  = og & 255;
        const int nt = o >> 7;
        const int r  = o & 127;
        const int h0 = (t & 127) * 8;               // k offset, 8 floats
        const int slab = h0 >> 5;
        const int hk = h0 & 31;
        const float* src = W + (size_t)og * NH + h0;
        float4 v0 = ((const float4*)src)[0];
        float4 v1 = ((const float4*)src)[1];
        __half2 h[4];
        h[0] = __floats2half2_rn(v0.x, v0.y);
        h[1] = __floats2half2_rn(v0.z, v0.w);
        h[2] = __floats2half2_rn(v1.x, v1.y);
        h[3] = __floats2half2_rn(v1.z, v1.w);
        __half* dst = W16t + ((((size_t)(e * 2 + nt) * NSLAB + slab) * 128 + r) * 32 + hk);
        *(uint4*)dst = *(uint4*)h;
    } else {
        // bin: single block, 256 threads x 32 items
        __shared__ int cs[1024];
        __shared__ int scnt[NE];
        __shared__ int scur[NE];
        for (int i = t; i < cmap_n && i < 1024; i += 256) cs[i] = c[i] & (NE - 1);
        if (t < NE) scnt[t] = 0;
        __syncthreads();
        int le[NB / 256];
        #pragma unroll
        for (int j = 0; j < NB / 256; j++) {
            int i = t + j * 256;
            int idx = num[i];
            idx = min(max(idx, 0), cmap_n - 1);
            le[j] = cs[idx];
            atomicAdd(&scnt[le[j]], 1);
        }
        __syncthreads();
        if (t == 0) {
            int acc = 0;
            g_off[0] = 0;
            #pragma unroll
            for (int e = 0; e < NE; e++) {
                scur[e] = acc;
                acc += scnt[e];
                g_off[e + 1] = acc;
                g_counts[e] = scnt[e];
            }
        }
        __syncthreads();
        #pragma unroll
        for (int j = 0; j < NB / 256; j++) {
            int pos = atomicAdd(&scur[le[j]], 1);
            g_perm[pos] = t + j * 256;
        }
    }
}

// ---------------- helpers ----------------
__device__ __forceinline__ uint32_t smem_u32(const void* p) {
    uint32_t a;
    asm("{ .reg .u64 t; cvta.to.shared.u64 t, %1; cvt.u32.u64 %0, t; }" : "=r"(a) : "l"(p));
    return a;
}

__device__ __forceinline__ void cpasync16(uint32_t dst, const void* src) {
    asm volatile("cp.async.cg.shared.global [%0], [%1], 16;" :: "r"(dst), "l"(src));
}

__device__ __forceinline__ void ldsm_x4(uint32_t r[4], uint32_t addr) {
    asm volatile("ldmatrix.sync.aligned.m8n8.x4.shared.b16 {%0,%1,%2,%3}, [%4];"
                 : "=r"(r[0]), "=r"(r[1]), "=r"(r[2]), "=r"(r[3]) : "r"(addr));
}

__device__ __forceinline__ void mma_f16(float c[4], const uint32_t a[4],
                                        uint32_t b0, uint32_t b1) {
    asm volatile(
        "mma.sync.aligned.m16n8k16.row.col.f32.f16.f16.f32 "
        "{%0,%1,%2,%3}, {%4,%5,%6,%7}, {%8,%9}, {%0,%1,%2,%3};"
        : "+f"(c[0]), "+f"(c[1]), "+f"(c[2]), "+f"(c[3])
        : "r"(a[0]), "r"(a[1]), "r"(a[2]), "r"(a[3]), "r"(b0), "r"(b1));
}

__device__ __forceinline__ void mbar_wait(uint32_t mbar, uint32_t parity) {
    asm volatile(
        "{\n\t.reg .pred P;\n\t"
        "W%=:\n\t"
        "mbarrier.try_wait.parity.acquire.cta.shared::cta.b64 P, [%0], %1, 0x989680;\n\t"
        "@!P bra W%=;\n\t"
        "}" :: "r"(mbar), "r"(parity) : "memory");
}

__device__ __forceinline__ float sigf(float v) { return 1.f / (1.f + __expf(-v)); }

// ---------------- fp16 GEMM + bias + sigmoid; B via cp.async.bulk ----------------
// grid = (2, 128, 16); dead tiles exit immediately.
__global__ __launch_bounds__(THREADS, 2)
void gemm_kernel(const float* __restrict__ bias, float* __restrict__ out) {
    const int e = blockIdx.z;
    const int rows = g_counts[e];
    const int m_start = blockIdx.y * BM;
    if (m_start >= rows) return;
    const int n_start = blockIdx.x * BN;
    const int base = g_off[e];

    extern __shared__ char smem[];
    const uint32_t sb = smem_u32(smem);
    float* bsm = (float*)(smem + BIAS_OFF);
    int*   prm = (int*)(smem + PRM_OFF);

    const int t    = threadIdx.x;
    const int lane = t & 31;
    const int wid  = t >> 5;
    const int g    = lane >> 2;
    const int tig  = lane & 3;
    const int g2   = lane >> 3;
    const int lr   = lane & 7;
    const int warp_m = (wid & 1) * 32;
    const int warp_n = (wid >> 1) * 32;

    if (t < BN) bsm[t] = bias[e * NO + n_start + t];
    if (t < BM) {
        int m = m_start + t;
        prm[t] = (m < rows) ? g_perm[base + m] : g_perm[base + m_start];
    }
    if (t == 0) {
        #pragma unroll
        for (int s = 0; s < STAGES; s++)
            asm volatile("mbarrier.init.shared.b64 [%0], 1;"
                         :: "r"(sb + MBAR_OFF + s * 8) : "memory");
    }
    __syncthreads();

    // A gather source: row prm[t>>2], 16B chunk (t&3)
    const __half* agp = x16 + (size_t)prm[t >> 2] * NH + (t & 3) * 8;
    const uint32_t adst = (uint32_t)((t >> 2) * 64 + (t & 3) * 16);
    // B bulk source: contiguous 8KB per slab
    const __half* bsrc = W16t + ((size_t)(e * 2 + blockIdx.x) * NSLAB) * (128 * 32);

    // ldmatrix offsets (packed 64B rows)
    uint32_t aoff[2], boff[2];
    #pragma unroll
    for (int mf = 0; mf < 2; mf++)
        aoff[mf] = (uint32_t)((warp_m + mf * 16 + (g2 & 1) * 8 + lr) * 64 + (g2 >> 1) * 16);
    #pragma unroll
    for (int p = 0; p < 2; p++)
        boff[p] = (uint32_t)((warp_n + p * 16 + (g2 >> 1) * 8 + lr) * 64 + (g2 & 1) * 16);

    float acc[2][4][4];
    #pragma unroll
    for (int i = 0; i < 2; i++)
        #pragma unroll
        for (int j = 0; j < 4; j++)
            #pragma unroll
            for (int q = 0; q < 4; q++) acc[i][j][q] = 0.f;

    auto issueA = [&](int ks, int s) {
        cpasync16(sb + A_OFF + s * A_STAGE_B + adst, agp + ks * BKS);
    };
    auto issueB = [&](int ks, int s) {   // t==0 only
        const uint32_t mb = sb + MBAR_OFF + s * 8;
        asm volatile("mbarrier.arrive.expect_tx.shared.b64 _, [%0], %1;"
                     :: "r"(mb), "r"((uint32_t)B_STAGE_B) : "memory");
        asm volatile(
            "cp.async.bulk.shared::cluster.global.mbarrier::complete_tx::bytes "
            "[%0], [%1], %2, [%3];"
            :: "r"(sb + B_OFF + s * B_STAGE_B), "l"(bsrc + (size_t)ks * (128 * 32)),
               "r"((uint32_t)B_STAGE_B), "r"(mb) : "memory");
    };

    // prologue: stages 0..2
    #pragma unroll
    for (int s = 0; s < STAGES - 1; s++) {
        issueA(s, s);
        asm volatile("cp.async.commit_group;");
        if (t == 0) issueB(s, s);
    }

    for (int ks = 0; ks < NSLAB; ks++) {
        asm volatile("cp.async.wait_group %0;" :: "n"(STAGES - 2) : "memory");
        const int s = ks & (STAGES - 1);
        mbar_wait(sb + MBAR_OFF + s * 8, (ks >> 2) & 1);
        __syncthreads();

        const uint32_t ab = sb + A_OFF + s * A_STAGE_B;
        const uint32_t bb = sb + B_OFF + s * B_STAGE_B;
        #pragma unroll
        for (int kk = 0; kk < 2; kk++) {
            uint32_t a[2][4], b[2][4];
            #pragma unroll
            for (int mf = 0; mf < 2; mf++) ldsm_x4(a[mf], ab + aoff[mf] + kk * 32);
            #pragma unroll
            for (int p = 0; p < 2; p++)   ldsm_x4(b[p], bb + boff[p] + kk * 32);
            #pragma unroll
            for (int mf = 0; mf < 2; mf++)
                #pragma unroll
                for (int nf = 0; nf < 4; nf++)
                    mma_f16(acc[mf][nf], a[mf], b[nf >> 1][(nf & 1) * 2],
                            b[nf >> 1][(nf & 1) * 2 + 1]);
        }
        __syncthreads();   // all warps done reading stage (ks+3)&3's previous contents

        const int ksn = ks + STAGES - 1;
        if (ksn < NSLAB) {
            issueA(ksn, ksn & (STAGES - 1));
            if (t == 0) issueB(ksn, ksn & (STAGES - 1));
        }
        asm volatile("cp.async.commit_group;");
    }

    // epilogue: bias + sigmoid, scatter rows through prm
    #pragma unroll
    for (int mf = 0; mf < 2; mf++) {
        #pragma unroll
        for (int h = 0; h < 2; h++) {
            const int rl = warp_m + mf * 16 + g + h * 8;
            if (m_start + rl < rows) {
                const int orow = prm[rl];
                #pragma unroll
                for (int nf = 0; nf < 4; nf++) {
                    const int col = warp_n + nf * 8 + 2 * tig;
                    float v0 = acc[mf][nf][h * 2 + 0] + bsm[col];
                    float v1 = acc[mf][nf][h * 2 + 1] + bsm[col + 1];
                    float2 o;
                    o.x = sigf(v0);
                    o.y = sigf(v1);
                    *(float2*)&out[(size_t)orow * NO + n_start + col] = o;
                }
            }
        }
    }
}

extern "C" void kernel_launch(void* const* d_in, const int* in_sizes, int n_in,
                              void* d_out, int out_size) {
    const float* x    = (const float*)d_in[0];   // [B, H]
    const float* W    = (const float*)d_in[1];   // [E, O, H]
    const float* bias = (const float*)d_in[2];   // [E, O]
    const int*   num  = (const int*)d_in[3];     // [B]    int32
    const int*   c    = (const int*)d_in[4];     // [CMAP] int32
    float* out = (float*)d_out;                  // [B, O]

    const int cmap_n = in_sizes[4];

    cudaFuncSetAttribute(gemm_kernel, cudaFuncAttributeMaxDynamicSharedMemorySize,
                         SMEM_TOTAL);

    prep_kernel<<<4097, 256>>>(x, W, num, c, cmap_n);

    dim3 grid(NO / BN, NB / BM, NE);   // (2, 128, 16)
    gemm_kernel<<<grid, THREADS, SMEM_TOTAL>>>(bias, out);
}

// round 11
// speedup vs baseline: 1.6914x; 1.6914x over previous
#include <cuda_runtime.h>
#include <cuda_fp16.h>
#include <cstdint>

// Problem constants.
#define NB 8192
#define NH 1024
#define NO 256
#define NE 16

// GEMM tiling: CTA = 64(M) x 128(N), K slabs of 32 halfs, 4-stage pipeline.
#define BM 64
#define BN 128
#define BKS 32
#define NSLAB (NH / BKS)   // 32
#define THREADS 256
#define STAGES 4
#define A_STAGE_B 4096                  // 64 rows x 64 B (swizzled chunks)
#define B_STAGE_B 8192                  // 128 rows x 64 B (swizzled chunks)
#define A_OFF 0
#define B_OFF (STAGES * A_STAGE_B)      // 16384
#define BIAS_OFF (B_OFF + STAGES * B_STAGE_B)   // 49152
#define PRM_OFF (BIAS_OFF + BN * 4)             // 49664
#define MBAR_OFF (PRM_OFF + BM * 4)             // 49920
#define SMEM_TOTAL (MBAR_OFF + 64)              // 49984

// --- scratch (no allocs allowed) ---
__device__ int    g_perm[NB];
__device__ int    g_off[NE + 1];
__device__ int    g_counts[NE];
__device__ __half x16[NB * NH];                    // x fp16, original order (plain layout)
__device__ __half W16t[NE * 2 * NSLAB * 128 * 32]; // W fp16 tiled [e][nt][slab][row][32], chunk-swizzled

// swizzle: 16B-chunk c in row r -> c ^ ((r>>1)&3)
#define SWZ(r, c) ((c) ^ (((r) >> 1) & 3))

// ---------------- fused prep: bin (1 block) + x convert + W convert ----------------
// grid = 4097 x 256: [0,2048) x rows, [2048,4096) W rows, 4096 = bin.
__global__ __launch_bounds__(256)
void prep_kernel(const float* __restrict__ x, const float* __restrict__ W,
                 const int* __restrict__ num, const int* __restrict__ c, int cmap_n) {
    const int b = blockIdx.x;
    const int t = threadIdx.x;
    if (b < 2048) {
        const int row = b * 4 + (t >> 6);
        const int col = (t & 63) * 16;
        const float* src = x + (size_t)row * NH + col;
        float4 v0 = ((const float4*)src)[0];
        float4 v1 = ((const float4*)src)[1];
        float4 v2 = ((const float4*)src)[2];
        float4 v3 = ((const float4*)src)[3];
        __half2 h[8];
        h[0] = __floats2half2_rn(v0.x, v0.y);
        h[1] = __floats2half2_rn(v0.z, v0.w);
        h[2] = __floats2half2_rn(v1.x, v1.y);
        h[3] = __floats2half2_rn(v1.z, v1.w);
        h[4] = __floats2half2_rn(v2.x, v2.y);
        h[5] = __floats2half2_rn(v2.z, v2.w);
        h[6] = __floats2half2_rn(v3.x, v3.y);
        h[7] = __floats2half2_rn(v3.z, v3.w);
        __half* dst = x16 + (size_t)row * NH + col;
        ((uint4*)dst)[0] = *(uint4*)&h[0];
        ((uint4*)dst)[1] = *(uint4*)&h[4];
    } else if (b < 4096) {
        // W convert into tiled + swizzled layout: 2 global W rows per block
        const int og = (b - 2048) * 2 + (t >> 7);   // global W row 0..4095
        const int e  = og >> 8;
        const int o  = og & 255;
        const int nt = o >> 7;
        const int r  = o & 127;
        const int h0 = (t & 127) * 8;               // k offset (8 floats)
        const int slab = h0 >> 5;
        const int cj = (h0 & 31) >> 3;              // 16B chunk 0..3
        const float* src = W + (size_t)og * NH + h0;
        float4 v0 = ((const float4*)src)[0];
        float4 v1 = ((const float4*)src)[1];
        __half2 h[4];
        h[0] = __floats2half2_rn(v0.x, v0.y);
        h[1] = __floats2half2_rn(v0.z, v0.w);
        h[2] = __floats2half2_rn(v1.x, v1.y);
        h[3] = __floats2half2_rn(v1.z, v1.w);
        __half* dst = W16t + ((((size_t)(e * 2 + nt) * NSLAB + slab) * 128 + r) * 32
                              + SWZ(r, cj) * 8);
        *(uint4*)dst = *(uint4*)h;
    } else {
        // bin: single block
        __shared__ int cs[1024];
        __shared__ int scnt[NE];
        __shared__ int scur[NE];
        for (int i = t; i < cmap_n && i < 1024; i += 256) cs[i] = c[i] & (NE - 1);
        if (t < NE) scnt[t] = 0;
        __syncthreads();
        int le[NB / 256];
        #pragma unroll
        for (int j = 0; j < NB / 256; j++) {
            int i = t + j * 256;
            int idx = num[i];
            idx = min(max(idx, 0), cmap_n - 1);
            le[j] = cs[idx];
            atomicAdd(&scnt[le[j]], 1);
        }
        __syncthreads();
        if (t == 0) {
            int acc = 0;
            g_off[0] = 0;
            #pragma unroll
            for (int e = 0; e < NE; e++) {
                scur[e] = acc;
                acc += scnt[e];
                g_off[e + 1] = acc;
                g_counts[e] = scnt[e];
            }
        }
        __syncthreads();
        #pragma unroll
        for (int j = 0; j < NB / 256; j++) {
            int pos = atomicAdd(&scur[le[j]], 1);
            g_perm[pos] = t + j * 256;
        }
    }
}

// ---------------- helpers ----------------
__device__ __forceinline__ uint32_t smem_u32(const void* p) {
    uint32_t a;
    asm("{ .reg .u64 t; cvta.to.shared.u64 t, %1; cvt.u32.u64 %0, t; }" : "=r"(a) : "l"(p));
    return a;
}

__device__ __forceinline__ void cpasync16(uint32_t dst, const void* src) {
    asm volatile("cp.async.cg.shared.global [%0], [%1], 16;" :: "r"(dst), "l"(src));
}

__device__ __forceinline__ void ldsm_x4(uint32_t r[4], uint32_t addr) {
    asm volatile("ldmatrix.sync.aligned.m8n8.x4.shared.b16 {%0,%1,%2,%3}, [%4];"
                 : "=r"(r[0]), "=r"(r[1]), "=r"(r[2]), "=r"(r[3]) : "r"(addr));
}

__device__ __forceinline__ void mma_f16(float c[4], const uint32_t a[4],
                                        uint32_t b0, uint32_t b1) {
    asm volatile(
        "mma.sync.aligned.m16n8k16.row.col.f32.f16.f16.f32 "
        "{%0,%1,%2,%3}, {%4,%5,%6,%7}, {%8,%9}, {%0,%1,%2,%3};"
        : "+f"(c[0]), "+f"(c[1]), "+f"(c[2]), "+f"(c[3])
        : "r"(a[0]), "r"(a[1]), "r"(a[2]), "r"(a[3]), "r"(b0), "r"(b1));
}

__device__ __forceinline__ void mbar_wait(uint32_t mbar, uint32_t parity) {
    asm volatile(
        "{\n\t.reg .pred P;\n\t"
        "W%=:\n\t"
        "mbarrier.try_wait.parity.acquire.cta.shared::cta.b64 P, [%0], %1, 0x989680;\n\t"
        "@!P bra W%=;\n\t"
        "}" :: "r"(mbar), "r"(parity) : "memory");
}

__device__ __forceinline__ float sigf(float v) { return 1.f / (1.f + __expf(-v)); }

// ---------------- fp16 GEMM + bias + sigmoid; swizzled smem, bulk B ----------------
// grid = (2, 128, 16); dead tiles exit immediately.
__global__ __launch_bounds__(THREADS, 2)
void gemm_kernel(const float* __restrict__ bias, float* __restrict__ out) {
    const int e = blockIdx.z;
    const int rows = g_counts[e];
    const int m_start = blockIdx.y * BM;
    if (m_start >= rows) return;
    const int n_start = blockIdx.x * BN;
    const int base = g_off[e];

    extern __shared__ char smem[];
    const uint32_t sb = smem_u32(smem);
    float* bsm = (float*)(smem + BIAS_OFF);
    int*   prm = (int*)(smem + PRM_OFF);

    const int t    = threadIdx.x;
    const int lane = t & 31;
    const int wid  = t >> 5;
    const int g    = lane >> 2;
    const int tig  = lane & 3;
    const int g2   = lane >> 3;
    const int lr   = lane & 7;
    const int warp_m = (wid & 1) * 32;
    const int warp_n = (wid >> 1) * 32;

    if (t < BN) bsm[t] = bias[e * NO + n_start + t];
    if (t < BM) {
        int m = m_start + t;
        prm[t] = (m < rows) ? g_perm[base + m] : g_perm[base + m_start];
    }
    if (t == 0) {
        #pragma unroll
        for (int s = 0; s < STAGES; s++)
            asm volatile("mbarrier.init.shared.b64 [%0], 1;"
                         :: "r"(sb + MBAR_OFF + s * 8) : "memory");
    }
    __syncthreads();

    // A staging: thread t -> row t>>2, chunk t&3 (swizzled dst)
    const int arow = t >> 2;
    const __half* agp = x16 + (size_t)prm[arow] * NH + (t & 3) * 8;
    const uint32_t adst = (uint32_t)(arow * 64 + SWZ(arow, t & 3) * 16);
    // B bulk source: contiguous, pre-swizzled 8KB per slab
    const __half* bsrc = W16t + ((size_t)(e * 2 + blockIdx.x) * NSLAB) * (128 * 32);

    // ldmatrix row bases + swizzle keys
    uint32_t arb[2], asw[2], brb[2], bsw[2];
    const uint32_t cba = g2 >> 1;   // A chunk base (0/1)
    const uint32_t cbb = g2 & 1;    // B chunk base (0/1)
    #pragma unroll
    for (int mf = 0; mf < 2; mf++) {
        const int r = warp_m + mf * 16 + (g2 & 1) * 8 + lr;
        arb[mf] = (uint32_t)(r * 64);
        asw[mf] = (uint32_t)((r >> 1) & 3);
    }
    #pragma unroll
    for (int p = 0; p < 2; p++) {
        const int r = warp_n + p * 16 + (g2 >> 1) * 8 + lr;
        brb[p] = (uint32_t)(r * 64);
        bsw[p] = (uint32_t)((r >> 1) & 3);
    }

    float acc[2][4][4];
    #pragma unroll
    for (int i = 0; i < 2; i++)
        #pragma unroll
        for (int j = 0; j < 4; j++)
            #pragma unroll
            for (int q = 0; q < 4; q++) acc[i][j][q] = 0.f;

    auto issueA = [&](int ks, int s) {
        cpasync16(sb + A_OFF + s * A_STAGE_B + adst, agp + ks * BKS);
    };
    auto issueB = [&](int ks, int s) {   // t==0 only
        const uint32_t mb = sb + MBAR_OFF + s * 8;
        asm volatile("mbarrier.arrive.expect_tx.shared.b64 _, [%0], %1;"
                     :: "r"(mb), "r"((uint32_t)B_STAGE_B) : "memory");
        asm volatile(
            "cp.async.bulk.shared::cluster.global.mbarrier::complete_tx::bytes "
            "[%0], [%1], %2, [%3];"
            :: "r"(sb + B_OFF + s * B_STAGE_B), "l"(bsrc + (size_t)ks * (128 * 32)),
               "r"((uint32_t)B_STAGE_B), "r"(mb) : "memory");
    };

    // prologue: stages 0..2
    #pragma unroll
    for (int s = 0; s < STAGES - 1; s++) {
        issueA(s, s);
        asm volatile("cp.async.commit_group;");
        if (t == 0) issueB(s, s);
    }

    for (int ks = 0; ks < NSLAB; ks++) {
        asm volatile("cp.async.wait_group %0;" :: "n"(STAGES - 2) : "memory");
        const int s = ks & (STAGES - 1);
        mbar_wait(sb + MBAR_OFF + s * 8, (ks >> 2) & 1);
        __syncthreads();   // single barrier: orders data-ready AND stage-reuse

        const uint32_t ab = sb + A_OFF + s * A_STAGE_B;
        const uint32_t bb = sb + B_OFF + s * B_STAGE_B;
        #pragma unroll
        for (int kk = 0; kk < 2; kk++) {
            uint32_t a[2][4], b[2][4];
            #pragma unroll
            for (int mf = 0; mf < 2; mf++)
                ldsm_x4(a[mf], ab + arb[mf] + (((cba | (kk << 1)) ^ asw[mf]) << 4));
            #pragma unroll
            for (int p = 0; p < 2; p++)
                ldsm_x4(b[p], bb + brb[p] + (((cbb | (kk << 1)) ^ bsw[p]) << 4));
            #pragma unroll
            for (int mf = 0; mf < 2; mf++)
                #pragma unroll
                for (int nf = 0; nf < 4; nf++)
                    mma_f16(acc[mf][nf], a[mf], b[nf >> 1][(nf & 1) * 2],
                            b[nf >> 1][(nf & 1) * 2 + 1]);
        }

        const int ksn = ks + STAGES - 1;
        if (ksn < NSLAB) {
            issueA(ksn, ksn & (STAGES - 1));
            if (t == 0) issueB(ksn, ksn & (STAGES - 1));
        }
        asm volatile("cp.async.commit_group;");
    }

    // epilogue: bias + sigmoid, scatter rows through prm
    #pragma unroll
    for (int mf = 0; mf < 2; mf++) {
        #pragma unroll
        for (int h = 0; h < 2; h++) {
            const int rl = warp_m + mf * 16 + g + h * 8;
            if (m_start + rl < rows) {
                const int orow = prm[rl];
                #pragma unroll
                for (int nf = 0; nf < 4; nf++) {
                    const int col = warp_n + nf * 8 + 2 * tig;
                    float v0 = acc[mf][nf][h * 2 + 0] + bsm[col];
                    float v1 = acc[mf][nf][h * 2 + 1] + bsm[col + 1];
                    float2 o;
                    o.x = sigf(v0);
                    o.y = sigf(v1);
                    *(float2*)&out[(size_t)orow * NO + n_start + col] = o;
                }
            }
        }
    }
}

extern "C" void kernel_launch(void* const* d_in, const int* in_sizes, int n_in,
                              void* d_out, int out_size) {
    const float* x    = (const float*)d_in[0];   // [B, H]
    const float* W    = (const float*)d_in[1];   // [E, O, H]
    const float* bias = (const float*)d_in[2];   // [E, O]
    const int*   num  = (const int*)d_in[3];     // [B]    int32
    const int*   c    = (const int*)d_in[4];     // [CMAP] int32
    float* out = (float*)d_out;                  // [B, O]

    const int cmap_n = in_sizes[4];

    cudaFuncSetAttribute(gemm_kernel, cudaFuncAttributeMaxDynamicSharedMemorySize,
                         SMEM_TOTAL);

    prep_kernel<<<4097, 256>>>(x, W, num, c, cmap_n);

    dim3 grid(NO / BN, NB / BM, NE);   // (2, 128, 16)
    gemm_kernel<<<grid, THREADS, SMEM_TOTAL>>>(bias, out);
}